// round 6
// baseline (speedup 1.0000x reference)
#include <cuda_runtime.h>
#include <cuda_fp16.h>
#include <math.h>

// Problem constants
#define NEXP 64
#define TOPK 4
#define HDIM 2048
#define IDIM 1536
#define GSZ  128
#define NTOK 1024
#define CAP  128
#define A_TOT (NTOK*TOPK)        // 4096 assignments
#define NCHUNK (A_TOT/256)       // 16
#define HW   (HDIM/8)            // 256 packed words per gate/up row
#define IW   (IDIM/8)            // 192 packed words per down row
#define NGH  (HDIM/GSZ)          // 16
#define NGI  (IDIM/GSZ)          // 12

// Scratch (static device globals; no runtime allocation)
__device__ int    g_topk_idx[A_TOT];
__device__ float  g_topk_w[A_TOT];
__device__ int    g_pos[A_TOT];
__device__ int    g_rowlist[NEXP*CAP];
__device__ int    g_count[NEXP];
__device__ int    g_chunkhist[NCHUNK][NEXP];
__device__ __half g_xh[(size_t)NTOK*HDIM];          // x in fp16
__device__ __half g_hbh[(size_t)NEXP*CAP*IDIM];     // routed h (fp16)
__device__ __half g_hshh[(size_t)NTOK*IDIM];        // shared h (fp16)
__device__ float  g_yrout[(size_t)NEXP*CAP*HDIM];   // routed down output

// ---------------------------------------------------------------------------
// helpers
// ---------------------------------------------------------------------------
__device__ __forceinline__ unsigned sptr(const void* p) {
    return (unsigned)__cvta_generic_to_shared(p);
}

__device__ __forceinline__ void ldsm4(unsigned a, unsigned& r0, unsigned& r1,
                                      unsigned& r2, unsigned& r3) {
    asm volatile("ldmatrix.sync.aligned.m8n8.x4.shared.b16 {%0,%1,%2,%3}, [%4];"
                 : "=r"(r0), "=r"(r1), "=r"(r2), "=r"(r3) : "r"(a));
}

__device__ __forceinline__ void mma16816(float* c, const unsigned* a,
                                         unsigned b0, unsigned b1) {
    asm volatile("mma.sync.aligned.m16n8k16.row.col.f32.f16.f16.f32 "
                 "{%0,%1,%2,%3},{%4,%5,%6,%7},{%8,%9},{%0,%1,%2,%3};"
                 : "+f"(c[0]), "+f"(c[1]), "+f"(c[2]), "+f"(c[3])
                 : "r"(a[0]), "r"(a[1]), "r"(a[2]), "r"(a[3]), "r"(b0), "r"(b1));
}

// FP4 e2m1 nibble b -> fp16 bits ((b&7)<<9 | (b&8)<<12); value = fp16 * 2^14.
// Scale pre-multiplied by 2^14. Produces 4 half2 (k-pairs 01,23,45,67).
__device__ __forceinline__ void dq8(unsigned w, __half2 s, unsigned* o) {
    unsigned lo = w & 0x0F0F0F0Fu;
    unsigned hi = (w >> 4) & 0x0F0F0F0Fu;
    unsigned fl = ((lo << 1) & 0x0E0E0E0Eu) | ((lo << 4) & 0x80808080u);
    unsigned fh = ((hi << 1) & 0x0E0E0E0Eu) | ((hi << 4) & 0x80808080u);
    unsigned m0 = __byte_perm(fl, fh, 0x5140);
    unsigned m1 = __byte_perm(fl, fh, 0x7362);
    unsigned t0 = __byte_perm(m0, 0, 0x1404);
    unsigned t1 = __byte_perm(m0, 0, 0x3424);
    unsigned t2 = __byte_perm(m1, 0, 0x1404);
    unsigned t3 = __byte_perm(m1, 0, 0x3424);
    __half2 h0 = __hmul2(*reinterpret_cast<__half2*>(&t0), s);
    __half2 h1 = __hmul2(*reinterpret_cast<__half2*>(&t1), s);
    __half2 h2 = __hmul2(*reinterpret_cast<__half2*>(&t2), s);
    __half2 h3 = __hmul2(*reinterpret_cast<__half2*>(&t3), s);
    o[0] = *reinterpret_cast<unsigned*>(&h0);
    o[1] = *reinterpret_cast<unsigned*>(&h1);
    o[2] = *reinterpret_cast<unsigned*>(&h2);
    o[3] = *reinterpret_cast<unsigned*>(&h3);
}

__device__ __forceinline__ float silu_f(float v) {
    return v / (1.f + expf(-v));
}

// ---------------------------------------------------------------------------
__global__ __launch_bounds__(256) void xcvt_kernel(const float* __restrict__ x)
{
    size_t i = ((size_t)blockIdx.x * 256 + threadIdx.x) * 4;
    float4 v = *(const float4*)(x + i);
    *(__half2*)&g_xh[i]     = __floats2half2_rn(v.x, v.y);
    *(__half2*)&g_xh[i + 2] = __floats2half2_rn(v.z, v.w);
}

// ---------------------------------------------------------------------------
// Router (fp32 exact top-k)
// ---------------------------------------------------------------------------
__global__ __launch_bounds__(256) void router_kernel(const float* __restrict__ x,
                                                     const float* __restrict__ gate_w)
{
    __shared__ float sx[16][33];
    __shared__ float sw[64][33];
    __shared__ float slog[16][65];
    int t0  = blockIdx.x * 16;
    int tid = threadIdx.x;
    int e   = tid & 63;
    int tg  = tid >> 6;
    float acc[4] = {0.f, 0.f, 0.f, 0.f};

    for (int hc = 0; hc < HDIM; hc += 32) {
        __syncthreads();
#pragma unroll
        for (int k = 0; k < 8; k++) {
            int idx = tid + k * 256;
            sw[idx >> 5][idx & 31] = gate_w[(idx >> 5) * HDIM + hc + (idx & 31)];
        }
#pragma unroll
        for (int k = 0; k < 2; k++) {
            int idx = tid + k * 256;
            sx[idx >> 5][idx & 31] = x[(size_t)(t0 + (idx >> 5)) * HDIM + hc + (idx & 31)];
        }
        __syncthreads();
#pragma unroll 8
        for (int kk = 0; kk < 32; kk++) {
            float wv = sw[e][kk];
#pragma unroll
            for (int j = 0; j < 4; j++) acc[j] += sx[tg * 4 + j][kk] * wv;
        }
    }
#pragma unroll
    for (int j = 0; j < 4; j++) slog[tg * 4 + j][e] = acc[j];
    __syncthreads();

    if (tid < 16) {
        int tt = tid;
        unsigned long long used = 0ull;
        int idxk[TOPK]; float valk[TOPK];
#pragma unroll
        for (int k = 0; k < TOPK; k++) {
            float bv = -1e30f; int bi = 0;
            for (int ee = 0; ee < NEXP; ee++) {
                float v = slog[tt][ee];
                if (((used >> ee) & 1ull) == 0 && v > bv) { bv = v; bi = ee; }
            }
            used |= (1ull << bi);
            idxk[k] = bi; valk[k] = bv;
        }
        float s = 0.f, w[TOPK];
#pragma unroll
        for (int k = 0; k < TOPK; k++) { w[k] = expf(valk[k] - valk[0]); s += w[k]; }
#pragma unroll
        for (int k = 0; k < TOPK; k++) {
            g_topk_idx[(t0 + tt) * TOPK + k] = idxk[k];
            g_topk_w[(t0 + tt) * TOPK + k]  = w[k] / s;
        }
    }
}

__global__ void zero_counts_kernel()
{
    if (threadIdx.x < NEXP) g_count[threadIdx.x] = 0;
}

// ---------------------------------------------------------------------------
// Dispatch stage 1: per-chunk expert histograms (+ global counts).
// ---------------------------------------------------------------------------
__global__ __launch_bounds__(256) void hist_kernel()
{
    __shared__ int cnt[NEXP];
    int tid = threadIdx.x;
    if (tid < NEXP) cnt[tid] = 0;
    __syncthreads();
    int e = g_topk_idx[blockIdx.x * 256 + tid];
    atomicAdd(&cnt[e], 1);
    __syncthreads();
    if (tid < NEXP) {
        g_chunkhist[blockIdx.x][tid] = cnt[tid];
        atomicAdd(&g_count[tid], cnt[tid]);
    }
}

// ---------------------------------------------------------------------------
// Dispatch stage 2: pos[a] = chunk-prefix + within-chunk prefix (stable).
// ---------------------------------------------------------------------------
__global__ __launch_bounds__(256) void dispatch_kernel()
{
    __shared__ unsigned char ef[256];
    int tid = threadIdx.x;
    int a = blockIdx.x * 256 + tid;
    int e = g_topk_idx[a];
    ef[tid] = (unsigned char)e;
    __syncthreads();

    int base = 0;
    for (int c = 0; c < (int)blockIdx.x; c++) base += g_chunkhist[c][e];
    int local = 0;
    for (int j = 0; j < tid; j++) local += (ef[j] == (unsigned char)e) ? 1 : 0;
    int p = base + local;
    g_pos[a] = p;
    if (p < CAP) g_rowlist[e * CAP + p] = a;
}

// ---------------------------------------------------------------------------
// GEMM1 (tensor cores, double-buffered): h = silu(x Wg^T) * (x Wu^T).
// Tile 64(M) x 64(N), K-chunk 64, 2-stage smem pipeline, ONE barrier/chunk.
// Warps 2(M) x 4(N), each 32x16.
// ---------------------------------------------------------------------------
struct SmemG1 {
    __half X [2][64][72];
    __half Wg[2][64][72];
    __half Wu[2][64][72];
    int    rows[128];
};

template<bool ROUTED>
__global__ __launch_bounds__(256) void gemm1_mma(
    const int* __restrict__ gpk, const int* __restrict__ upk,
    const float* __restrict__ gsc, const float* __restrict__ usc)
{
    extern __shared__ char smraw[];
    SmemG1& sm = *reinterpret_cast<SmemG1*>(smraw);

    int tid = threadIdx.x;
    int ic0 = blockIdx.y * 64;
    int e   = blockIdx.x;

    int n; const int *gp, *up; const float *gs, *us;
    if (ROUTED) {
        n  = min(g_count[e], CAP);
        if (n == 0) return;
        gp = gpk + (size_t)e * IDIM * HW;
        up = upk + (size_t)e * IDIM * HW;
        gs = gsc + (size_t)e * NGH * IDIM;
        us = usc + (size_t)e * NGH * IDIM;
    } else { n = 64; gp = gpk; up = upk; gs = gsc; us = usc; }

    __half* hout = ROUTED ? g_hbh : g_hshh;
    int rbase    = ROUTED ? e * CAP : e * 64;

    if (ROUTED) {
        if (tid < 128)
            sm.rows[tid] = (tid < n) ? (g_rowlist[e * CAP + tid] >> 2) : 0;
        __syncthreads();
    }

    int w = tid >> 5, l = tid & 31;
    int mb = (w & 1) * 32, nb = (w >> 1) * 16;
    int xrow = tid >> 2, xseg = tid & 3;
    int i_w  = ic0 + xrow;

    for (int r0 = 0; r0 < (ROUTED ? n : 64); r0 += 64) {
        int nrem = ROUTED ? (n - r0) : 64;
        int tok;
        if (ROUTED) tok = sm.rows[r0 + min(xrow, nrem - 1)];
        else        tok = e * 64 + xrow;

        float accg[2][2][4], accu[2][2][4];
#pragma unroll
        for (int i = 0; i < 2; i++)
#pragma unroll
            for (int j = 0; j < 2; j++)
#pragma unroll
                for (int q = 0; q < 4; q++) { accg[i][j][q] = 0.f; accu[i][j][q] = 0.f; }

        uint4 xa, xb; int2 gw, uw; float sgf, suf;
        auto LOAD = [&](int kc) {
            const uint4* xp = (const uint4*)(g_xh + (size_t)tok * HDIM + kc + xseg * 16);
            xa = xp[0]; xb = xp[1];
            gw = ((const int2*)(gp + (size_t)i_w * HW + (kc >> 3)))[xseg];
            uw = ((const int2*)(up + (size_t)i_w * HW + (kc >> 3)))[xseg];
            int grp = kc >> 7;
            sgf = gs[grp * IDIM + i_w];
            suf = us[grp * IDIM + i_w];
        };
        auto STORE = [&](int st) {
            *(uint4*)&sm.X[st][xrow][xseg * 16]     = xa;
            *(uint4*)&sm.X[st][xrow][xseg * 16 + 8] = xb;
            __half2 s2g = __float2half2_rn(sgf * 16384.f);
            __half2 s2u = __float2half2_rn(suf * 16384.f);
            unsigned o[4];
            dq8((unsigned)gw.x, s2g, o);
            *(uint2*)&sm.Wg[st][xrow][xseg * 16]      = make_uint2(o[0], o[1]);
            *(uint2*)&sm.Wg[st][xrow][xseg * 16 + 4]  = make_uint2(o[2], o[3]);
            dq8((unsigned)gw.y, s2g, o);
            *(uint2*)&sm.Wg[st][xrow][xseg * 16 + 8]  = make_uint2(o[0], o[1]);
            *(uint2*)&sm.Wg[st][xrow][xseg * 16 + 12] = make_uint2(o[2], o[3]);
            dq8((unsigned)uw.x, s2u, o);
            *(uint2*)&sm.Wu[st][xrow][xseg * 16]      = make_uint2(o[0], o[1]);
            *(uint2*)&sm.Wu[st][xrow][xseg * 16 + 4]  = make_uint2(o[2], o[3]);
            dq8((unsigned)uw.y, s2u, o);
            *(uint2*)&sm.Wu[st][xrow][xseg * 16 + 8]  = make_uint2(o[0], o[1]);
            *(uint2*)&sm.Wu[st][xrow][xseg * 16 + 12] = make_uint2(o[2], o[3]);
        };

        const int NC = HDIM / 64;
        LOAD(0);
        STORE(0);
        LOAD(64);
        __syncthreads();
#pragma unroll 1
        for (int c = 0; c < NC; c++) {
            int cur = c & 1;
            if (c + 1 < NC) {
                STORE(cur ^ 1);                      // writes other stage: overlaps mma
                if (c + 2 < NC) LOAD((c + 2) * 64);
            }
#pragma unroll
            for (int ks = 0; ks < 4; ks++) {
                int k0 = ks * 16;
                unsigned a0[4], a1[4], bg[4], bu[4];
                ldsm4(sptr(&sm.X[cur][mb      + (l & 7) + ((l >> 3) & 1) * 8][k0 + (l >> 4) * 8]),
                      a0[0], a0[1], a0[2], a0[3]);
                ldsm4(sptr(&sm.X[cur][mb + 16 + (l & 7) + ((l >> 3) & 1) * 8][k0 + (l >> 4) * 8]),
                      a1[0], a1[1], a1[2], a1[3]);
                ldsm4(sptr(&sm.Wg[cur][nb + ((l >> 4) << 3) + (l & 7)][k0 + ((l >> 3) & 1) * 8]),
                      bg[0], bg[1], bg[2], bg[3]);
                ldsm4(sptr(&sm.Wu[cur][nb + ((l >> 4) << 3) + (l & 7)][k0 + ((l >> 3) & 1) * 8]),
                      bu[0], bu[1], bu[2], bu[3]);
                mma16816(accg[0][0], a0, bg[0], bg[1]);
                mma16816(accg[0][1], a0, bg[2], bg[3]);
                mma16816(accg[1][0], a1, bg[0], bg[1]);
                mma16816(accg[1][1], a1, bg[2], bg[3]);
                mma16816(accu[0][0], a0, bu[0], bu[1]);
                mma16816(accu[0][1], a0, bu[2], bu[3]);
                mma16816(accu[1][0], a1, bu[0], bu[1]);
                mma16816(accu[1][1], a1, bu[2], bu[3]);
            }
            __syncthreads();
        }

        // epilogue: silu(g)*u -> fp16
        int qm = l >> 2, qn = (l & 3) * 2;
#pragma unroll
        for (int mi = 0; mi < 2; mi++)
#pragma unroll
            for (int ni = 0; ni < 2; ni++) {
                int lr   = mb + mi * 16 + qm;
                int icol = ic0 + nb + ni * 8 + qn;
                float* g4 = accg[mi][ni]; float* u4 = accu[mi][ni];
                if (!ROUTED || lr < nrem) {
                    float h0 = silu_f(g4[0]) * u4[0];
                    float h1 = silu_f(g4[1]) * u4[1];
                    *(__half2*)&hout[(size_t)(rbase + r0 + lr) * IDIM + icol] =
                        __floats2half2_rn(h0, h1);
                }
                if (!ROUTED || lr + 8 < nrem) {
                    float h2 = silu_f(g4[2]) * u4[2];
                    float h3 = silu_f(g4[3]) * u4[3];
                    *(__half2*)&hout[(size_t)(rbase + r0 + lr + 8) * IDIM + icol] =
                        __floats2half2_rn(h2, h3);
                }
            }
        if (!ROUTED) break;
    }
}

// ---------------------------------------------------------------------------
// GEMM2 (tensor cores, double-buffered): y = h @ Wd^T. Tile 64x64, chunk 64.
// ---------------------------------------------------------------------------
template<bool ROUTED>
__global__ __launch_bounds__(256) void gemm2_mma(
    const int* __restrict__ dpk, const float* __restrict__ dsc,
    float* __restrict__ y)
{
    __shared__ __half sH[2][64][72];
    __shared__ __half sW[2][64][72];

    int tid = threadIdx.x;
    int oc0 = blockIdx.y * 64;
    int e   = blockIdx.x;

    int n; const int* dp; const float* ds;
    if (ROUTED) {
        n  = min(g_count[e], CAP);
        if (n == 0) return;
        dp = dpk + (size_t)e * HDIM * IW;
        ds = dsc + (size_t)e * NGI * HDIM;
    } else { n = 64; dp = dpk; ds = dsc; }

    const __half* hin = ROUTED ? g_hbh : g_hshh;
    float* yout       = ROUTED ? g_yrout : y;
    int rbase         = ROUTED ? e * CAP : e * 64;

    int w = tid >> 5, l = tid & 31;
    int mb = (w & 1) * 32, nb = (w >> 1) * 16;
    int xrow = tid >> 2, xseg = tid & 3;
    int o_w  = oc0 + xrow;

    for (int r0 = 0; r0 < n; r0 += 64) {
        int nrem = ROUTED ? (n - r0) : 64;
        int hr = rbase + r0 + (ROUTED ? min(xrow, nrem - 1) : xrow);

        float acc[2][2][4];
#pragma unroll
        for (int i = 0; i < 2; i++)
#pragma unroll
            for (int j = 0; j < 2; j++)
#pragma unroll
                for (int q = 0; q < 4; q++) acc[i][j][q] = 0.f;

        uint4 ha, hb; int2 dw; float sdf;
        auto LOAD = [&](int kc) {
            const uint4* hp = (const uint4*)(hin + (size_t)hr * IDIM + kc + xseg * 16);
            ha = hp[0]; hb = hp[1];
            dw = ((const int2*)(dp + (size_t)o_w * IW + (kc >> 3)))[xseg];
            sdf = ds[(kc >> 7) * HDIM + o_w];
        };
        auto STORE = [&](int st) {
            *(uint4*)&sH[st][xrow][xseg * 16]     = ha;
            *(uint4*)&sH[st][xrow][xseg * 16 + 8] = hb;
            __half2 s2 = __float2half2_rn(sdf * 16384.f);
            unsigned o[4];
            dq8((unsigned)dw.x, s2, o);
            *(uint2*)&sW[st][xrow][xseg * 16]      = make_uint2(o[0], o[1]);
            *(uint2*)&sW[st][xrow][xseg * 16 + 4]  = make_uint2(o[2], o[3]);
            dq8((unsigned)dw.y, s2, o);
            *(uint2*)&sW[st][xrow][xseg * 16 + 8]  = make_uint2(o[0], o[1]);
            *(uint2*)&sW[st][xrow][xseg * 16 + 12] = make_uint2(o[2], o[3]);
        };

        const int NC = IDIM / 64;
        LOAD(0);
        STORE(0);
        LOAD(64);
        __syncthreads();
#pragma unroll 1
        for (int c = 0; c < NC; c++) {
            int cur = c & 1;
            if (c + 1 < NC) {
                STORE(cur ^ 1);
                if (c + 2 < NC) LOAD((c + 2) * 64);
            }
#pragma unroll
            for (int ks = 0; ks < 4; ks++) {
                int k0 = ks * 16;
                unsigned a0[4], a1[4], bw[4];
                ldsm4(sptr(&sH[cur][mb      + (l & 7) + ((l >> 3) & 1) * 8][k0 + (l >> 4) * 8]),
                      a0[0], a0[1], a0[2], a0[3]);
                ldsm4(sptr(&sH[cur][mb + 16 + (l & 7) + ((l >> 3) & 1) * 8][k0 + (l >> 4) * 8]),
                      a1[0], a1[1], a1[2], a1[3]);
                ldsm4(sptr(&sW[cur][nb + ((l >> 4) << 3) + (l & 7)][k0 + ((l >> 3) & 1) * 8]),
                      bw[0], bw[1], bw[2], bw[3]);
                mma16816(acc[0][0], a0, bw[0], bw[1]);
                mma16816(acc[0][1], a0, bw[2], bw[3]);
                mma16816(acc[1][0], a1, bw[0], bw[1]);
                mma16816(acc[1][1], a1, bw[2], bw[3]);
            }
            __syncthreads();
        }

        int qm = l >> 2, qn = (l & 3) * 2;
#pragma unroll
        for (int mi = 0; mi < 2; mi++)
#pragma unroll
            for (int ni = 0; ni < 2; ni++) {
                int lr   = mb + mi * 16 + qm;
                int ocol = oc0 + nb + ni * 8 + qn;
                float* c4 = acc[mi][ni];
                if (!ROUTED || lr < nrem)
                    *(float2*)&yout[(size_t)(rbase + r0 + lr) * HDIM + ocol] =
                        make_float2(c4[0], c4[1]);
                if (!ROUTED || lr + 8 < nrem)
                    *(float2*)&yout[(size_t)(rbase + r0 + lr + 8) * HDIM + ocol] =
                        make_float2(c4[2], c4[3]);
            }
        if (!ROUTED) break;
    }
}

// ---------------------------------------------------------------------------
// Combine: y[t] += sum_k tw[t,k] * yrout[slot(t,k)]
// ---------------------------------------------------------------------------
__global__ __launch_bounds__(256) void combine_kernel(float* __restrict__ y)
{
    int t = blockIdx.x;
    __shared__ int   slot4[TOPK];
    __shared__ float w4[TOPK];
    int tid = threadIdx.x;
    if (tid < TOPK) {
        int a = t * TOPK + tid;
        int e = g_topk_idx[a];
        int p = g_pos[a];
        slot4[tid] = (p < CAP) ? (e * CAP + p) : -1;
        w4[tid]    = g_topk_w[a];
    }
    __syncthreads();
    for (int hh = tid; hh < HDIM; hh += 256) {
        float acc = y[(size_t)t * HDIM + hh];
#pragma unroll
        for (int k = 0; k < TOPK; k++) {
            int s = slot4[k];
            if (s >= 0) acc += w4[k] * g_yrout[(size_t)s * HDIM + hh];
        }
        y[(size_t)t * HDIM + hh] = acc;
    }
}

// ---------------------------------------------------------------------------
extern "C" void kernel_launch(void* const* d_in, const int* in_sizes, int n_in,
                              void* d_out, int out_size)
{
    const float* x              = (const float*)d_in[0];
    const float* gate_w         = (const float*)d_in[1];
    const float* gate_scales    = (const float*)d_in[2];
    const float* up_scales      = (const float*)d_in[3];
    const float* down_scales    = (const float*)d_in[4];
    const float* sh_gate_scales = (const float*)d_in[5];
    const float* sh_up_scales   = (const float*)d_in[6];
    const float* sh_down_scales = (const float*)d_in[7];
    const int*   gate_packed    = (const int*)d_in[8];
    const int*   up_packed      = (const int*)d_in[9];
    const int*   down_packed    = (const int*)d_in[10];
    const int*   sh_gate_packed = (const int*)d_in[11];
    const int*   sh_up_packed   = (const int*)d_in[12];
    const int*   sh_down_packed = (const int*)d_in[13];
    float* y = (float*)d_out;

    const int g1_smem = (int)sizeof(SmemG1);
    cudaFuncSetAttribute(gemm1_mma<false>,
                         cudaFuncAttributeMaxDynamicSharedMemorySize, g1_smem);
    cudaFuncSetAttribute(gemm1_mma<true>,
                         cudaFuncAttributeMaxDynamicSharedMemorySize, g1_smem);

    xcvt_kernel<<<NTOK * HDIM / 1024, 256>>>(x);
    router_kernel<<<NTOK / 16, 256>>>(x, gate_w);
    zero_counts_kernel<<<1, 64>>>();
    hist_kernel<<<NCHUNK, 256>>>();
    dispatch_kernel<<<NCHUNK, 256>>>();

    // Shared expert
    gemm1_mma<false><<<dim3(NTOK / 64, IDIM / 64), 256, g1_smem>>>(
        sh_gate_packed, sh_up_packed, sh_gate_scales, sh_up_scales);
    gemm2_mma<false><<<dim3(NTOK / 64, HDIM / 64), 256>>>(
        sh_down_packed, sh_down_scales, y);

    // Routed experts
    gemm1_mma<true><<<dim3(NEXP, IDIM / 64), 256, g1_smem>>>(
        gate_packed, up_packed, gate_scales, up_scales);
    gemm2_mma<true><<<dim3(NEXP, HDIM / 64), 256>>>(
        down_packed, down_scales, y);

    combine_kernel<<<NTOK, 256>>>(y);
}

// round 7
// speedup vs baseline: 1.4119x; 1.4119x over previous
#include <cuda_runtime.h>
#include <cuda_fp16.h>
#include <math.h>

// Problem constants
#define NEXP 64
#define TOPK 4
#define HDIM 2048
#define IDIM 1536
#define GSZ  128
#define NTOK 1024
#define CAP  128
#define A_TOT (NTOK*TOPK)        // 4096 assignments
#define NCHUNK (A_TOT/256)       // 16
#define HW   (HDIM/8)            // 256 packed words per gate/up row
#define IW   (IDIM/8)            // 192 packed words per down row
#define NGH  (HDIM/GSZ)          // 16
#define NGI  (IDIM/GSZ)          // 12
#define KPAD 136                 // 128 + 8 halves pad (272B row stride)

// Scratch (static device globals; no runtime allocation)
__device__ int    g_topk_idx[A_TOT];
__device__ float  g_topk_w[A_TOT];
__device__ int    g_pos[A_TOT];
__device__ int    g_rowlist[NEXP*CAP];
__device__ int    g_count[NEXP];
__device__ int    g_chunkhist[NCHUNK][NEXP];
__device__ __half g_xh[(size_t)NTOK*HDIM];          // x in fp16
__device__ __half g_hbh[(size_t)NEXP*CAP*IDIM];     // routed h (fp16)
__device__ __half g_hshh[(size_t)NTOK*IDIM];        // shared h (fp16)
__device__ float  g_yrout[(size_t)NEXP*CAP*HDIM];   // routed down output

// ---------------------------------------------------------------------------
// helpers
// ---------------------------------------------------------------------------
__device__ __forceinline__ unsigned sptr(const void* p) {
    return (unsigned)__cvta_generic_to_shared(p);
}

__device__ __forceinline__ void ldsm4(unsigned a, unsigned& r0, unsigned& r1,
                                      unsigned& r2, unsigned& r3) {
    asm volatile("ldmatrix.sync.aligned.m8n8.x4.shared.b16 {%0,%1,%2,%3}, [%4];"
                 : "=r"(r0), "=r"(r1), "=r"(r2), "=r"(r3) : "r"(a));
}

__device__ __forceinline__ void mma16816(float* c, const unsigned* a,
                                         unsigned b0, unsigned b1) {
    asm volatile("mma.sync.aligned.m16n8k16.row.col.f32.f16.f16.f32 "
                 "{%0,%1,%2,%3},{%4,%5,%6,%7},{%8,%9},{%0,%1,%2,%3};"
                 : "+f"(c[0]), "+f"(c[1]), "+f"(c[2]), "+f"(c[3])
                 : "r"(a[0]), "r"(a[1]), "r"(a[2]), "r"(a[3]), "r"(b0), "r"(b1));
}

// FP4 e2m1 nibble b -> fp16 bits ((b&7)<<9 | (b&8)<<12); value = fp16 * 2^14.
// Scale pre-multiplied by 2^14. Produces 4 half2 (k-pairs 01,23,45,67).
__device__ __forceinline__ void dq8(unsigned w, __half2 s, unsigned* o) {
    unsigned lo = w & 0x0F0F0F0Fu;
    unsigned hi = (w >> 4) & 0x0F0F0F0Fu;
    unsigned fl = ((lo << 1) & 0x0E0E0E0Eu) | ((lo << 4) & 0x80808080u);
    unsigned fh = ((hi << 1) & 0x0E0E0E0Eu) | ((hi << 4) & 0x80808080u);
    unsigned m0 = __byte_perm(fl, fh, 0x5140);
    unsigned m1 = __byte_perm(fl, fh, 0x7362);
    unsigned t0 = __byte_perm(m0, 0, 0x1404);
    unsigned t1 = __byte_perm(m0, 0, 0x3424);
    unsigned t2 = __byte_perm(m1, 0, 0x1404);
    unsigned t3 = __byte_perm(m1, 0, 0x3424);
    __half2 h0 = __hmul2(*reinterpret_cast<__half2*>(&t0), s);
    __half2 h1 = __hmul2(*reinterpret_cast<__half2*>(&t1), s);
    __half2 h2 = __hmul2(*reinterpret_cast<__half2*>(&t2), s);
    __half2 h3 = __hmul2(*reinterpret_cast<__half2*>(&t3), s);
    o[0] = *reinterpret_cast<unsigned*>(&h0);
    o[1] = *reinterpret_cast<unsigned*>(&h1);
    o[2] = *reinterpret_cast<unsigned*>(&h2);
    o[3] = *reinterpret_cast<unsigned*>(&h3);
}

__device__ __forceinline__ float silu_f(float v) {
    return v / (1.f + expf(-v));
}

// ---------------------------------------------------------------------------
__global__ __launch_bounds__(256) void xcvt_kernel(const float* __restrict__ x)
{
    size_t i = ((size_t)blockIdx.x * 256 + threadIdx.x) * 4;
    float4 v = *(const float4*)(x + i);
    *(__half2*)&g_xh[i]     = __floats2half2_rn(v.x, v.y);
    *(__half2*)&g_xh[i + 2] = __floats2half2_rn(v.z, v.w);
}

// ---------------------------------------------------------------------------
// Router (fp32 exact top-k)
// ---------------------------------------------------------------------------
__global__ __launch_bounds__(256) void router_kernel(const float* __restrict__ x,
                                                     const float* __restrict__ gate_w)
{
    __shared__ float sx[16][33];
    __shared__ float sw[64][33];
    __shared__ float slog[16][65];
    int t0  = blockIdx.x * 16;
    int tid = threadIdx.x;
    int e   = tid & 63;
    int tg  = tid >> 6;
    float acc[4] = {0.f, 0.f, 0.f, 0.f};

    for (int hc = 0; hc < HDIM; hc += 32) {
        __syncthreads();
#pragma unroll
        for (int k = 0; k < 8; k++) {
            int idx = tid + k * 256;
            sw[idx >> 5][idx & 31] = gate_w[(idx >> 5) * HDIM + hc + (idx & 31)];
        }
#pragma unroll
        for (int k = 0; k < 2; k++) {
            int idx = tid + k * 256;
            sx[idx >> 5][idx & 31] = x[(size_t)(t0 + (idx >> 5)) * HDIM + hc + (idx & 31)];
        }
        __syncthreads();
#pragma unroll 8
        for (int kk = 0; kk < 32; kk++) {
            float wv = sw[e][kk];
#pragma unroll
            for (int j = 0; j < 4; j++) acc[j] += sx[tg * 4 + j][kk] * wv;
        }
    }
#pragma unroll
    for (int j = 0; j < 4; j++) slog[tg * 4 + j][e] = acc[j];
    __syncthreads();

    if (tid < 16) {
        int tt = tid;
        unsigned long long used = 0ull;
        int idxk[TOPK]; float valk[TOPK];
#pragma unroll
        for (int k = 0; k < TOPK; k++) {
            float bv = -1e30f; int bi = 0;
            for (int ee = 0; ee < NEXP; ee++) {
                float v = slog[tt][ee];
                if (((used >> ee) & 1ull) == 0 && v > bv) { bv = v; bi = ee; }
            }
            used |= (1ull << bi);
            idxk[k] = bi; valk[k] = bv;
        }
        float s = 0.f, w[TOPK];
#pragma unroll
        for (int k = 0; k < TOPK; k++) { w[k] = expf(valk[k] - valk[0]); s += w[k]; }
#pragma unroll
        for (int k = 0; k < TOPK; k++) {
            g_topk_idx[(t0 + tt) * TOPK + k] = idxk[k];
            g_topk_w[(t0 + tt) * TOPK + k]  = w[k] / s;
        }
    }
}

__global__ void zero_counts_kernel()
{
    if (threadIdx.x < NEXP) g_count[threadIdx.x] = 0;
}

// ---------------------------------------------------------------------------
// Dispatch stage 1: per-chunk expert histograms (+ global counts).
// ---------------------------------------------------------------------------
__global__ __launch_bounds__(256) void hist_kernel()
{
    __shared__ int cnt[NEXP];
    int tid = threadIdx.x;
    if (tid < NEXP) cnt[tid] = 0;
    __syncthreads();
    int e = g_topk_idx[blockIdx.x * 256 + tid];
    atomicAdd(&cnt[e], 1);
    __syncthreads();
    if (tid < NEXP) {
        g_chunkhist[blockIdx.x][tid] = cnt[tid];
        atomicAdd(&g_count[tid], cnt[tid]);
    }
}

// ---------------------------------------------------------------------------
// Dispatch stage 2: pos[a] = chunk-prefix + within-chunk prefix (stable).
// ---------------------------------------------------------------------------
__global__ __launch_bounds__(256) void dispatch_kernel()
{
    __shared__ unsigned char ef[256];
    int tid = threadIdx.x;
    int a = blockIdx.x * 256 + tid;
    int e = g_topk_idx[a];
    ef[tid] = (unsigned char)e;
    __syncthreads();

    int base = 0;
    for (int c = 0; c < (int)blockIdx.x; c++) base += g_chunkhist[c][e];
    int local = 0;
    for (int j = 0; j < tid; j++) local += (ef[j] == (unsigned char)e) ? 1 : 0;
    int p = base + local;
    g_pos[a] = p;
    if (p < CAP) g_rowlist[e * CAP + p] = a;
}

// ---------------------------------------------------------------------------
// GEMM1 (tensor cores): h = silu(x Wg^T) * (x Wu^T). Tile 64(M) x 64(N),
// K-chunk 128 (one scale group), two-sync pattern, 8 warps 2(M) x 4(N).
// ---------------------------------------------------------------------------
struct SmemG1 {
    __half X [64][KPAD];
    __half Wg[64][KPAD];
    __half Wu[64][KPAD];
    int    rows[128];
};

template<bool ROUTED>
__global__ __launch_bounds__(256, 2) void gemm1_mma(
    const int* __restrict__ gpk, const int* __restrict__ upk,
    const float* __restrict__ gsc, const float* __restrict__ usc)
{
    extern __shared__ char smraw[];
    SmemG1& sm = *reinterpret_cast<SmemG1*>(smraw);

    int tid = threadIdx.x;
    int ic0 = blockIdx.y * 64;
    int e   = blockIdx.x;

    int n; const int *gp, *up; const float *gs, *us;
    if (ROUTED) {
        n  = min(g_count[e], CAP);
        if (n == 0) return;
        gp = gpk + (size_t)e * IDIM * HW;
        up = upk + (size_t)e * IDIM * HW;
        gs = gsc + (size_t)e * NGH * IDIM;
        us = usc + (size_t)e * NGH * IDIM;
    } else { n = 64; gp = gpk; up = upk; gs = gsc; us = usc; }

    __half* hout = ROUTED ? g_hbh : g_hshh;
    int rbase    = ROUTED ? e * CAP : e * 64;

    if (ROUTED) {
        if (tid < 128)
            sm.rows[tid] = (tid < n) ? (g_rowlist[e * CAP + tid] >> 2) : 0;
        __syncthreads();
    }

    int w = tid >> 5, l = tid & 31;
    int mb = (w & 1) * 32, nb = (w >> 1) * 16;
    int xrow = tid >> 2, xseg = tid & 3;    // 64 rows x 4 segs of 32 halves
    int i_w  = ic0 + xrow;

    for (int r0 = 0; r0 < (ROUTED ? n : 64); r0 += 64) {
        int nrem = ROUTED ? (n - r0) : 64;
        int tok;
        if (ROUTED) tok = sm.rows[r0 + min(xrow, nrem - 1)];
        else        tok = e * 64 + xrow;

        float accg[2][2][4], accu[2][2][4];
#pragma unroll
        for (int i = 0; i < 2; i++)
#pragma unroll
            for (int j = 0; j < 2; j++)
#pragma unroll
                for (int q = 0; q < 4; q++) { accg[i][j][q] = 0.f; accu[i][j][q] = 0.f; }

        uint4 xa[4]; int4 gw, uw; float sgf, suf;
        auto LOAD = [&](int c) {
            int kc = c * 128;
            const uint4* xp = (const uint4*)(g_xh + (size_t)tok * HDIM + kc + xseg * 32);
#pragma unroll
            for (int j = 0; j < 4; j++) xa[j] = xp[j];
            gw = ((const int4*)(gp + (size_t)i_w * HW + c * 16))[xseg];
            uw = ((const int4*)(up + (size_t)i_w * HW + c * 16))[xseg];
            sgf = gs[c * IDIM + i_w];
            suf = us[c * IDIM + i_w];
        };
        auto STORE = [&]() {
#pragma unroll
            for (int j = 0; j < 4; j++)
                *(uint4*)&sm.X[xrow][xseg * 32 + j * 8] = xa[j];
            __half2 s2g = __float2half2_rn(sgf * 16384.f);
            __half2 s2u = __float2half2_rn(suf * 16384.f);
            unsigned o[4];
            int gwv[4] = {gw.x, gw.y, gw.z, gw.w};
            int uwv[4] = {uw.x, uw.y, uw.z, uw.w};
#pragma unroll
            for (int j = 0; j < 4; j++) {
                dq8((unsigned)gwv[j], s2g, o);
                *(uint4*)&sm.Wg[xrow][xseg * 32 + j * 8] =
                    make_uint4(o[0], o[1], o[2], o[3]);
            }
#pragma unroll
            for (int j = 0; j < 4; j++) {
                dq8((unsigned)uwv[j], s2u, o);
                *(uint4*)&sm.Wu[xrow][xseg * 32 + j * 8] =
                    make_uint4(o[0], o[1], o[2], o[3]);
            }
        };

        const int NC = HDIM / 128;   // 16 chunks
        LOAD(0);
        for (int c = 0; c < NC; c++) {
            __syncthreads();
            STORE();
            __syncthreads();
            if (c + 1 < NC) LOAD(c + 1);
#pragma unroll
            for (int ks = 0; ks < 8; ks++) {
                int k0 = ks * 16;
                unsigned a0[4], a1[4], bg[4], bu[4];
                ldsm4(sptr(&sm.X[mb      + (l & 7) + ((l >> 3) & 1) * 8][k0 + (l >> 4) * 8]),
                      a0[0], a0[1], a0[2], a0[3]);
                ldsm4(sptr(&sm.X[mb + 16 + (l & 7) + ((l >> 3) & 1) * 8][k0 + (l >> 4) * 8]),
                      a1[0], a1[1], a1[2], a1[3]);
                ldsm4(sptr(&sm.Wg[nb + ((l >> 4) << 3) + (l & 7)][k0 + ((l >> 3) & 1) * 8]),
                      bg[0], bg[1], bg[2], bg[3]);
                ldsm4(sptr(&sm.Wu[nb + ((l >> 4) << 3) + (l & 7)][k0 + ((l >> 3) & 1) * 8]),
                      bu[0], bu[1], bu[2], bu[3]);
                mma16816(accg[0][0], a0, bg[0], bg[1]);
                mma16816(accg[0][1], a0, bg[2], bg[3]);
                mma16816(accg[1][0], a1, bg[0], bg[1]);
                mma16816(accg[1][1], a1, bg[2], bg[3]);
                mma16816(accu[0][0], a0, bu[0], bu[1]);
                mma16816(accu[0][1], a0, bu[2], bu[3]);
                mma16816(accu[1][0], a1, bu[0], bu[1]);
                mma16816(accu[1][1], a1, bu[2], bu[3]);
            }
        }

        // epilogue: silu(g)*u -> fp16
        int qm = l >> 2, qn = (l & 3) * 2;
#pragma unroll
        for (int mi = 0; mi < 2; mi++)
#pragma unroll
            for (int ni = 0; ni < 2; ni++) {
                int lr   = mb + mi * 16 + qm;
                int icol = ic0 + nb + ni * 8 + qn;
                float* g4 = accg[mi][ni]; float* u4 = accu[mi][ni];
                if (!ROUTED || lr < nrem) {
                    float h0 = silu_f(g4[0]) * u4[0];
                    float h1 = silu_f(g4[1]) * u4[1];
                    *(__half2*)&hout[(size_t)(rbase + r0 + lr) * IDIM + icol] =
                        __floats2half2_rn(h0, h1);
                }
                if (!ROUTED || lr + 8 < nrem) {
                    float h2 = silu_f(g4[2]) * u4[2];
                    float h3 = silu_f(g4[3]) * u4[3];
                    *(__half2*)&hout[(size_t)(rbase + r0 + lr + 8) * IDIM + icol] =
                        __floats2half2_rn(h2, h3);
                }
            }
        if (!ROUTED) break;
        __syncthreads();   // protect smem before next pass refill
    }
}

// ---------------------------------------------------------------------------
// GEMM2 (tensor cores): y = h @ Wd^T. Tile 64x64, K-chunk 128, two-sync.
// ---------------------------------------------------------------------------
template<bool ROUTED>
__global__ __launch_bounds__(256, 2) void gemm2_mma(
    const int* __restrict__ dpk, const float* __restrict__ dsc,
    float* __restrict__ y)
{
    __shared__ __half sH[64][KPAD];
    __shared__ __half sW[64][KPAD];

    int tid = threadIdx.x;
    int oc0 = blockIdx.y * 64;
    int e   = blockIdx.x;

    int n; const int* dp; const float* ds;
    if (ROUTED) {
        n  = min(g_count[e], CAP);
        if (n == 0) return;
        dp = dpk + (size_t)e * HDIM * IW;
        ds = dsc + (size_t)e * NGI * HDIM;
    } else { n = 64; dp = dpk; ds = dsc; }

    const __half* hin = ROUTED ? g_hbh : g_hshh;
    float* yout       = ROUTED ? g_yrout : y;
    int rbase         = ROUTED ? e * CAP : e * 64;

    int w = tid >> 5, l = tid & 31;
    int mb = (w & 1) * 32, nb = (w >> 1) * 16;
    int xrow = tid >> 2, xseg = tid & 3;
    int o_w  = oc0 + xrow;

    for (int r0 = 0; r0 < n; r0 += 64) {
        int nrem = ROUTED ? (n - r0) : 64;
        int hr = rbase + r0 + (ROUTED ? min(xrow, nrem - 1) : xrow);

        float acc[2][2][4];
#pragma unroll
        for (int i = 0; i < 2; i++)
#pragma unroll
            for (int j = 0; j < 2; j++)
#pragma unroll
                for (int q = 0; q < 4; q++) acc[i][j][q] = 0.f;

        uint4 ha[4]; int4 dw; float sdf;
        auto LOAD = [&](int c) {
            int kc = c * 128;
            const uint4* hp = (const uint4*)(hin + (size_t)hr * IDIM + kc + xseg * 32);
#pragma unroll
            for (int j = 0; j < 4; j++) ha[j] = hp[j];
            dw = ((const int4*)(dp + (size_t)o_w * IW + c * 16))[xseg];
            sdf = ds[c * HDIM + o_w];
        };
        auto STORE = [&]() {
#pragma unroll
            for (int j = 0; j < 4; j++)
                *(uint4*)&sH[xrow][xseg * 32 + j * 8] = ha[j];
            __half2 s2 = __float2half2_rn(sdf * 16384.f);
            unsigned o[4];
            int dwv[4] = {dw.x, dw.y, dw.z, dw.w};
#pragma unroll
            for (int j = 0; j < 4; j++) {
                dq8((unsigned)dwv[j], s2, o);
                *(uint4*)&sW[xrow][xseg * 32 + j * 8] =
                    make_uint4(o[0], o[1], o[2], o[3]);
            }
        };

        const int NC = IDIM / 128;   // 12 chunks
        LOAD(0);
        for (int c = 0; c < NC; c++) {
            __syncthreads();
            STORE();
            __syncthreads();
            if (c + 1 < NC) LOAD(c + 1);
#pragma unroll
            for (int ks = 0; ks < 8; ks++) {
                int k0 = ks * 16;
                unsigned a0[4], a1[4], bw[4];
                ldsm4(sptr(&sH[mb      + (l & 7) + ((l >> 3) & 1) * 8][k0 + (l >> 4) * 8]),
                      a0[0], a0[1], a0[2], a0[3]);
                ldsm4(sptr(&sH[mb + 16 + (l & 7) + ((l >> 3) & 1) * 8][k0 + (l >> 4) * 8]),
                      a1[0], a1[1], a1[2], a1[3]);
                ldsm4(sptr(&sW[nb + ((l >> 4) << 3) + (l & 7)][k0 + ((l >> 3) & 1) * 8]),
                      bw[0], bw[1], bw[2], bw[3]);
                mma16816(acc[0][0], a0, bw[0], bw[1]);
                mma16816(acc[0][1], a0, bw[2], bw[3]);
                mma16816(acc[1][0], a1, bw[0], bw[1]);
                mma16816(acc[1][1], a1, bw[2], bw[3]);
            }
        }

        int qm = l >> 2, qn = (l & 3) * 2;
#pragma unroll
        for (int mi = 0; mi < 2; mi++)
#pragma unroll
            for (int ni = 0; ni < 2; ni++) {
                int lr   = mb + mi * 16 + qm;
                int ocol = oc0 + nb + ni * 8 + qn;
                float* c4 = acc[mi][ni];
                if (!ROUTED || lr < nrem)
                    *(float2*)&yout[(size_t)(rbase + r0 + lr) * HDIM + ocol] =
                        make_float2(c4[0], c4[1]);
                if (!ROUTED || lr + 8 < nrem)
                    *(float2*)&yout[(size_t)(rbase + r0 + lr + 8) * HDIM + ocol] =
                        make_float2(c4[2], c4[3]);
            }
        if (!ROUTED) break;
        __syncthreads();
    }
}

// ---------------------------------------------------------------------------
// Combine: y[t] += sum_k tw[t,k] * yrout[slot(t,k)]
// ---------------------------------------------------------------------------
__global__ __launch_bounds__(256) void combine_kernel(float* __restrict__ y)
{
    int t = blockIdx.x;
    __shared__ int   slot4[TOPK];
    __shared__ float w4[TOPK];
    int tid = threadIdx.x;
    if (tid < TOPK) {
        int a = t * TOPK + tid;
        int e = g_topk_idx[a];
        int p = g_pos[a];
        slot4[tid] = (p < CAP) ? (e * CAP + p) : -1;
        w4[tid]    = g_topk_w[a];
    }
    __syncthreads();
    for (int hh = tid; hh < HDIM; hh += 256) {
        float acc = y[(size_t)t * HDIM + hh];
#pragma unroll
        for (int k = 0; k < TOPK; k++) {
            int s = slot4[k];
            if (s >= 0) acc += w4[k] * g_yrout[(size_t)s * HDIM + hh];
        }
        y[(size_t)t * HDIM + hh] = acc;
    }
}

// ---------------------------------------------------------------------------
extern "C" void kernel_launch(void* const* d_in, const int* in_sizes, int n_in,
                              void* d_out, int out_size)
{
    const float* x              = (const float*)d_in[0];
    const float* gate_w         = (const float*)d_in[1];
    const float* gate_scales    = (const float*)d_in[2];
    const float* up_scales      = (const float*)d_in[3];
    const float* down_scales    = (const float*)d_in[4];
    const float* sh_gate_scales = (const float*)d_in[5];
    const float* sh_up_scales   = (const float*)d_in[6];
    const float* sh_down_scales = (const float*)d_in[7];
    const int*   gate_packed    = (const int*)d_in[8];
    const int*   up_packed      = (const int*)d_in[9];
    const int*   down_packed    = (const int*)d_in[10];
    const int*   sh_gate_packed = (const int*)d_in[11];
    const int*   sh_up_packed   = (const int*)d_in[12];
    const int*   sh_down_packed = (const int*)d_in[13];
    float* y = (float*)d_out;

    const int g1_smem = (int)sizeof(SmemG1);
    cudaFuncSetAttribute(gemm1_mma<false>,
                         cudaFuncAttributeMaxDynamicSharedMemorySize, g1_smem);
    cudaFuncSetAttribute(gemm1_mma<true>,
                         cudaFuncAttributeMaxDynamicSharedMemorySize, g1_smem);

    xcvt_kernel<<<NTOK * HDIM / 1024, 256>>>(x);
    router_kernel<<<NTOK / 16, 256>>>(x, gate_w);
    zero_counts_kernel<<<1, 64>>>();
    hist_kernel<<<NCHUNK, 256>>>();
    dispatch_kernel<<<NCHUNK, 256>>>();

    // Shared expert
    gemm1_mma<false><<<dim3(NTOK / 64, IDIM / 64), 256, g1_smem>>>(
        sh_gate_packed, sh_up_packed, sh_gate_scales, sh_up_scales);
    gemm2_mma<false><<<dim3(NTOK / 64, HDIM / 64), 256>>>(
        sh_down_packed, sh_down_scales, y);

    // Routed experts
    gemm1_mma<true><<<dim3(NEXP, IDIM / 64), 256, g1_smem>>>(
        gate_packed, up_packed, gate_scales, up_scales);
    gemm2_mma<true><<<dim3(NEXP, HDIM / 64), 256>>>(
        down_packed, down_scales, y);

    combine_kernel<<<NTOK, 256>>>(y);
}

// round 8
// speedup vs baseline: 1.6363x; 1.1589x over previous
#include <cuda_runtime.h>
#include <cuda_fp16.h>
#include <math.h>

// Problem constants
#define NEXP 64
#define TOPK 4
#define HDIM 2048
#define IDIM 1536
#define GSZ  128
#define NTOK 1024
#define CAP  128
#define A_TOT (NTOK*TOPK)        // 4096 assignments
#define NCHUNK (A_TOT/256)       // 16
#define HW   (HDIM/8)            // 256 packed words per gate/up row
#define IW   (IDIM/8)            // 192 packed words per down row
#define NGH  (HDIM/GSZ)          // 16
#define NGI  (IDIM/GSZ)          // 12
#define NSHB1 (NTOK/64)          // 16 shared-expert token blocks

// Scratch (static device globals; no runtime allocation)
__device__ int    g_topk_idx[A_TOT];
__device__ float  g_topk_w[A_TOT];
__device__ int    g_pos[A_TOT];
__device__ int    g_rowlist[NEXP*CAP];
__device__ int    g_count[NEXP];
__device__ int    g_chunkhist[NCHUNK][NEXP];
__device__ __half g_xh[(size_t)NTOK*HDIM];          // x in fp16
__device__ __half g_hbh[(size_t)NEXP*CAP*IDIM];     // routed h (fp16)
__device__ __half g_hshh[(size_t)NTOK*IDIM];        // shared h (fp16)
__device__ float  g_yrout[(size_t)NEXP*CAP*HDIM];   // routed down output

// ---------------------------------------------------------------------------
// helpers
// ---------------------------------------------------------------------------
__device__ __forceinline__ unsigned sptr(const void* p) {
    return (unsigned)__cvta_generic_to_shared(p);
}

__device__ __forceinline__ void ldsm4(unsigned a, unsigned& r0, unsigned& r1,
                                      unsigned& r2, unsigned& r3) {
    asm volatile("ldmatrix.sync.aligned.m8n8.x4.shared.b16 {%0,%1,%2,%3}, [%4];"
                 : "=r"(r0), "=r"(r1), "=r"(r2), "=r"(r3) : "r"(a));
}

__device__ __forceinline__ void mma16816(float* c, const unsigned* a,
                                         unsigned b0, unsigned b1) {
    asm volatile("mma.sync.aligned.m16n8k16.row.col.f32.f16.f16.f32 "
                 "{%0,%1,%2,%3},{%4,%5,%6,%7},{%8,%9},{%0,%1,%2,%3};"
                 : "+f"(c[0]), "+f"(c[1]), "+f"(c[2]), "+f"(c[3])
                 : "r"(a[0]), "r"(a[1]), "r"(a[2]), "r"(a[3]), "r"(b0), "r"(b1));
}

// FP4 e2m1 nibble b -> fp16 bits ((b&7)<<9 | (b&8)<<12); value = fp16 * 2^14.
// Scale pre-multiplied by 2^14. Produces 4 half2 (k-pairs 01,23,45,67).
__device__ __forceinline__ void dq8(unsigned w, __half2 s, unsigned* o) {
    unsigned lo = w & 0x0F0F0F0Fu;
    unsigned hi = (w >> 4) & 0x0F0F0F0Fu;
    unsigned fl = ((lo << 1) & 0x0E0E0E0Eu) | ((lo << 4) & 0x80808080u);
    unsigned fh = ((hi << 1) & 0x0E0E0E0Eu) | ((hi << 4) & 0x80808080u);
    unsigned m0 = __byte_perm(fl, fh, 0x5140);
    unsigned m1 = __byte_perm(fl, fh, 0x7362);
    unsigned t0 = __byte_perm(m0, 0, 0x1404);
    unsigned t1 = __byte_perm(m0, 0, 0x3424);
    unsigned t2 = __byte_perm(m1, 0, 0x1404);
    unsigned t3 = __byte_perm(m1, 0, 0x3424);
    __half2 h0 = __hmul2(*reinterpret_cast<__half2*>(&t0), s);
    __half2 h1 = __hmul2(*reinterpret_cast<__half2*>(&t1), s);
    __half2 h2 = __hmul2(*reinterpret_cast<__half2*>(&t2), s);
    __half2 h3 = __hmul2(*reinterpret_cast<__half2*>(&t3), s);
    o[0] = *reinterpret_cast<unsigned*>(&h0);
    o[1] = *reinterpret_cast<unsigned*>(&h1);
    o[2] = *reinterpret_cast<unsigned*>(&h2);
    o[3] = *reinterpret_cast<unsigned*>(&h3);
}

__device__ __forceinline__ float silu_f(float v) {
    return v / (1.f + expf(-v));
}

// ---------------------------------------------------------------------------
__global__ __launch_bounds__(256) void xcvt_kernel(const float* __restrict__ x)
{
    size_t i = ((size_t)blockIdx.x * 256 + threadIdx.x) * 4;
    float4 v = *(const float4*)(x + i);
    *(__half2*)&g_xh[i]     = __floats2half2_rn(v.x, v.y);
    *(__half2*)&g_xh[i + 2] = __floats2half2_rn(v.z, v.w);
}

// ---------------------------------------------------------------------------
// Router (fp32 exact top-k)
// ---------------------------------------------------------------------------
__global__ __launch_bounds__(256) void router_kernel(const float* __restrict__ x,
                                                     const float* __restrict__ gate_w)
{
    __shared__ float sx[16][33];
    __shared__ float sw[64][33];
    __shared__ float slog[16][65];
    int t0  = blockIdx.x * 16;
    int tid = threadIdx.x;
    int e   = tid & 63;
    int tg  = tid >> 6;
    float acc[4] = {0.f, 0.f, 0.f, 0.f};

    for (int hc = 0; hc < HDIM; hc += 32) {
        __syncthreads();
#pragma unroll
        for (int k = 0; k < 8; k++) {
            int idx = tid + k * 256;
            sw[idx >> 5][idx & 31] = gate_w[(idx >> 5) * HDIM + hc + (idx & 31)];
        }
#pragma unroll
        for (int k = 0; k < 2; k++) {
            int idx = tid + k * 256;
            sx[idx >> 5][idx & 31] = x[(size_t)(t0 + (idx >> 5)) * HDIM + hc + (idx & 31)];
        }
        __syncthreads();
#pragma unroll 8
        for (int kk = 0; kk < 32; kk++) {
            float wv = sw[e][kk];
#pragma unroll
            for (int j = 0; j < 4; j++) acc[j] += sx[tg * 4 + j][kk] * wv;
        }
    }
#pragma unroll
    for (int j = 0; j < 4; j++) slog[tg * 4 + j][e] = acc[j];
    __syncthreads();

    if (tid < 16) {
        int tt = tid;
        unsigned long long used = 0ull;
        int idxk[TOPK]; float valk[TOPK];
#pragma unroll
        for (int k = 0; k < TOPK; k++) {
            float bv = -1e30f; int bi = 0;
            for (int ee = 0; ee < NEXP; ee++) {
                float v = slog[tt][ee];
                if (((used >> ee) & 1ull) == 0 && v > bv) { bv = v; bi = ee; }
            }
            used |= (1ull << bi);
            idxk[k] = bi; valk[k] = bv;
        }
        float s = 0.f, w[TOPK];
#pragma unroll
        for (int k = 0; k < TOPK; k++) { w[k] = expf(valk[k] - valk[0]); s += w[k]; }
#pragma unroll
        for (int k = 0; k < TOPK; k++) {
            g_topk_idx[(t0 + tt) * TOPK + k] = idxk[k];
            g_topk_w[(t0 + tt) * TOPK + k]  = w[k] / s;
        }
    }
}

__global__ void zero_counts_kernel()
{
    if (threadIdx.x < NEXP) g_count[threadIdx.x] = 0;
}

// ---------------------------------------------------------------------------
// Dispatch stage 1: per-chunk expert histograms (+ global counts).
// ---------------------------------------------------------------------------
__global__ __launch_bounds__(256) void hist_kernel()
{
    __shared__ int cnt[NEXP];
    int tid = threadIdx.x;
    if (tid < NEXP) cnt[tid] = 0;
    __syncthreads();
    int e = g_topk_idx[blockIdx.x * 256 + tid];
    atomicAdd(&cnt[e], 1);
    __syncthreads();
    if (tid < NEXP) {
        g_chunkhist[blockIdx.x][tid] = cnt[tid];
        atomicAdd(&g_count[tid], cnt[tid]);
    }
}

// ---------------------------------------------------------------------------
// Dispatch stage 2: pos[a] = chunk-prefix + within-chunk prefix (stable).
// ---------------------------------------------------------------------------
__global__ __launch_bounds__(256) void dispatch_kernel()
{
    __shared__ unsigned char ef[256];
    int tid = threadIdx.x;
    int a = blockIdx.x * 256 + tid;
    int e = g_topk_idx[a];
    ef[tid] = (unsigned char)e;
    __syncthreads();

    int base = 0;
    for (int c = 0; c < (int)blockIdx.x; c++) base += g_chunkhist[c][e];
    int local = 0;
    for (int j = 0; j < tid; j++) local += (ef[j] == (unsigned char)e) ? 1 : 0;
    int p = base + local;
    g_pos[a] = p;
    if (p < CAP) g_rowlist[e * CAP + p] = a;
}

// ---------------------------------------------------------------------------
// GEMM1 (tensor cores): h = silu(x Wg^T) * (x Wu^T), FP4 dequant to fp16.
// Block tile 64(M) x 64(N), K-chunk 64, 8 warps (2M x 4N of 32x16 warp tiles).
// Unified grid: blockIdx.x < NEXP -> routed expert; else shared token-block.
// ---------------------------------------------------------------------------
__global__ __launch_bounds__(256) void gemm1_mma(
    const int* __restrict__ gpk, const int* __restrict__ upk,
    const float* __restrict__ gsc, const float* __restrict__ usc,
    const int* __restrict__ sh_gpk, const int* __restrict__ sh_upk,
    const float* __restrict__ sh_gsc, const float* __restrict__ sh_usc)
{
    __shared__ __half sX [64][72];
    __shared__ __half sWg[64][72];
    __shared__ __half sWu[64][72];
    __shared__ int srows[64];

    int tid = threadIdx.x;
    int ic0 = blockIdx.y * 64;
    int e   = blockIdx.x;
    bool routed = (e < NEXP);

    int n; const int *gp, *up; const float *gs, *us;
    __half* hout; int rbase; int tokbase = 0;
    if (routed) {
        n  = min(g_count[e], CAP);
        if (n == 0) return;
        gp = gpk + (size_t)e * IDIM * HW;
        up = upk + (size_t)e * IDIM * HW;
        gs = gsc + (size_t)e * NGH * IDIM;
        us = usc + (size_t)e * NGH * IDIM;
        hout = g_hbh; rbase = e * CAP;
    } else {
        int ts = e - NEXP;
        n = 64; gp = sh_gpk; up = sh_upk; gs = sh_gsc; us = sh_usc;
        hout = g_hshh; rbase = ts * 64; tokbase = ts * 64;
    }

    int w = tid >> 5, l = tid & 31;
    int mb = (w & 1) * 32, nb = (w >> 1) * 16;
    int xrow = tid >> 2, xseg = tid & 3;
    int i_w  = ic0 + xrow;

    for (int r0 = 0; r0 < n; r0 += 64) {
        int nrem = routed ? (n - r0) : 64;
        __syncthreads();
        if (routed && tid < 64)
            srows[tid] = (r0 + tid < n) ? (g_rowlist[e * CAP + r0 + tid] >> 2) : 0;
        __syncthreads();

        float accg[2][2][4], accu[2][2][4];
#pragma unroll
        for (int i = 0; i < 2; i++)
#pragma unroll
            for (int j = 0; j < 2; j++)
#pragma unroll
                for (int q = 0; q < 4; q++) { accg[i][j][q] = 0.f; accu[i][j][q] = 0.f; }

        int tok;
        if (routed) tok = srows[min(xrow, nrem - 1)];
        else        tok = tokbase + xrow;

        uint4 xa, xb; int2 gw, uw; float sgf, suf;
        auto LOAD = [&](int kc) {
            const uint4* xp = (const uint4*)(g_xh + (size_t)tok * HDIM + kc + xseg * 16);
            xa = xp[0]; xb = xp[1];
            gw = ((const int2*)(gp + (size_t)i_w * HW + (kc >> 3)))[xseg];
            uw = ((const int2*)(up + (size_t)i_w * HW + (kc >> 3)))[xseg];
            int grp = kc >> 7;
            sgf = gs[grp * IDIM + i_w];
            suf = us[grp * IDIM + i_w];
        };
        auto STORE = [&]() {
            *(uint4*)&sX[xrow][xseg * 16]     = xa;
            *(uint4*)&sX[xrow][xseg * 16 + 8] = xb;
            __half2 s2g = __float2half2_rn(sgf * 16384.f);
            __half2 s2u = __float2half2_rn(suf * 16384.f);
            unsigned o[4];
            dq8((unsigned)gw.x, s2g, o);
            *(uint2*)&sWg[xrow][xseg * 16]      = make_uint2(o[0], o[1]);
            *(uint2*)&sWg[xrow][xseg * 16 + 4]  = make_uint2(o[2], o[3]);
            dq8((unsigned)gw.y, s2g, o);
            *(uint2*)&sWg[xrow][xseg * 16 + 8]  = make_uint2(o[0], o[1]);
            *(uint2*)&sWg[xrow][xseg * 16 + 12] = make_uint2(o[2], o[3]);
            dq8((unsigned)uw.x, s2u, o);
            *(uint2*)&sWu[xrow][xseg * 16]      = make_uint2(o[0], o[1]);
            *(uint2*)&sWu[xrow][xseg * 16 + 4]  = make_uint2(o[2], o[3]);
            dq8((unsigned)uw.y, s2u, o);
            *(uint2*)&sWu[xrow][xseg * 16 + 8]  = make_uint2(o[0], o[1]);
            *(uint2*)&sWu[xrow][xseg * 16 + 12] = make_uint2(o[2], o[3]);
        };

        LOAD(0);
        for (int c = 0; c < HDIM / 64; c++) {
            __syncthreads();
            STORE();
            __syncthreads();
            if (c + 1 < HDIM / 64) LOAD((c + 1) * 64);
#pragma unroll
            for (int ks = 0; ks < 4; ks++) {
                int k0 = ks * 16;
                unsigned a0[4], a1[4], bg[4], bu[4];
                ldsm4(sptr(&sX[mb      + (l & 7) + ((l >> 3) & 1) * 8][k0 + (l >> 4) * 8]),
                      a0[0], a0[1], a0[2], a0[3]);
                ldsm4(sptr(&sX[mb + 16 + (l & 7) + ((l >> 3) & 1) * 8][k0 + (l >> 4) * 8]),
                      a1[0], a1[1], a1[2], a1[3]);
                ldsm4(sptr(&sWg[nb + ((l >> 4) << 3) + (l & 7)][k0 + ((l >> 3) & 1) * 8]),
                      bg[0], bg[1], bg[2], bg[3]);
                ldsm4(sptr(&sWu[nb + ((l >> 4) << 3) + (l & 7)][k0 + ((l >> 3) & 1) * 8]),
                      bu[0], bu[1], bu[2], bu[3]);
                mma16816(accg[0][0], a0, bg[0], bg[1]);
                mma16816(accg[0][1], a0, bg[2], bg[3]);
                mma16816(accg[1][0], a1, bg[0], bg[1]);
                mma16816(accg[1][1], a1, bg[2], bg[3]);
                mma16816(accu[0][0], a0, bu[0], bu[1]);
                mma16816(accu[0][1], a0, bu[2], bu[3]);
                mma16816(accu[1][0], a1, bu[0], bu[1]);
                mma16816(accu[1][1], a1, bu[2], bu[3]);
            }
        }

        // epilogue: silu(g)*u -> fp16
        int qm = l >> 2, qn = (l & 3) * 2;
#pragma unroll
        for (int mi = 0; mi < 2; mi++)
#pragma unroll
            for (int ni = 0; ni < 2; ni++) {
                int lr   = mb + mi * 16 + qm;
                int icol = ic0 + nb + ni * 8 + qn;
                float* g4 = accg[mi][ni]; float* u4 = accu[mi][ni];
                if (!routed || lr < nrem) {
                    float h0 = silu_f(g4[0]) * u4[0];
                    float h1 = silu_f(g4[1]) * u4[1];
                    *(__half2*)&hout[(size_t)(rbase + r0 + lr) * IDIM + icol] =
                        __floats2half2_rn(h0, h1);
                }
                if (!routed || lr + 8 < nrem) {
                    float h2 = silu_f(g4[2]) * u4[2];
                    float h3 = silu_f(g4[3]) * u4[3];
                    *(__half2*)&hout[(size_t)(rbase + r0 + lr + 8) * IDIM + icol] =
                        __floats2half2_rn(h2, h3);
                }
            }
        if (!routed) break;
    }
}

// ---------------------------------------------------------------------------
// GEMM2 (tensor cores): y = h @ Wd^T. Unified grid like gemm1.
// ---------------------------------------------------------------------------
__global__ __launch_bounds__(256) void gemm2_mma(
    const int* __restrict__ dpk, const float* __restrict__ dsc,
    const int* __restrict__ sh_dpk, const float* __restrict__ sh_dsc,
    float* __restrict__ y)
{
    __shared__ __half sH[2][64][72];
    __shared__ __half sW[2][64][72];

    int tid = threadIdx.x;
    int oc0 = blockIdx.y * 64;
    int e   = blockIdx.x;
    bool routed = (e < NEXP);

    int n; const int* dp; const float* ds;
    const __half* hin; float* yout; int rbase;
    if (routed) {
        n  = min(g_count[e], CAP);
        if (n == 0) return;
        dp = dpk + (size_t)e * HDIM * IW;
        ds = dsc + (size_t)e * NGI * HDIM;
        hin = g_hbh; yout = g_yrout; rbase = e * CAP;
    } else {
        int ts = e - NEXP;
        n = 64; dp = sh_dpk; ds = sh_dsc;
        hin = g_hshh; yout = y; rbase = ts * 64;
    }

    int w = tid >> 5, l = tid & 31;
    int mb = (w & 1) * 32, nb = (w >> 1) * 16;
    int xrow = tid >> 2, xseg = tid & 3;
    int o_w  = oc0 + xrow;

    for (int r0 = 0; r0 < n; r0 += 64) {
        int nrem = routed ? (n - r0) : 64;
        int hr = rbase + r0 + (routed ? min(xrow, nrem - 1) : xrow);

        float acc[2][2][4];
#pragma unroll
        for (int i = 0; i < 2; i++)
#pragma unroll
            for (int j = 0; j < 2; j++)
#pragma unroll
                for (int q = 0; q < 4; q++) acc[i][j][q] = 0.f;

        uint4 ha, hb; int2 dw; float sdf;
        auto LOAD = [&](int kc) {
            const uint4* hp = (const uint4*)(hin + (size_t)hr * IDIM + kc + xseg * 16);
            ha = hp[0]; hb = hp[1];
            dw = ((const int2*)(dp + (size_t)o_w * IW + (kc >> 3)))[xseg];
            sdf = ds[(kc >> 7) * HDIM + o_w];
        };
        auto STORE = [&](int st) {
            *(uint4*)&sH[st][xrow][xseg * 16]     = ha;
            *(uint4*)&sH[st][xrow][xseg * 16 + 8] = hb;
            __half2 s2 = __float2half2_rn(sdf * 16384.f);
            unsigned o[4];
            dq8((unsigned)dw.x, s2, o);
            *(uint2*)&sW[st][xrow][xseg * 16]      = make_uint2(o[0], o[1]);
            *(uint2*)&sW[st][xrow][xseg * 16 + 4]  = make_uint2(o[2], o[3]);
            dq8((unsigned)dw.y, s2, o);
            *(uint2*)&sW[st][xrow][xseg * 16 + 8]  = make_uint2(o[0], o[1]);
            *(uint2*)&sW[st][xrow][xseg * 16 + 12] = make_uint2(o[2], o[3]);
        };

        LOAD(0);
        for (int c = 0; c < IDIM / 64; c++) {
            __syncthreads();
            STORE(0);
            __syncthreads();
            if (c + 1 < IDIM / 64) LOAD((c + 1) * 64);
#pragma unroll
            for (int ks = 0; ks < 4; ks++) {
                int k0 = ks * 16;
                unsigned a0[4], a1[4], bw[4];
                ldsm4(sptr(&sH[0][mb      + (l & 7) + ((l >> 3) & 1) * 8][k0 + (l >> 4) * 8]),
                      a0[0], a0[1], a0[2], a0[3]);
                ldsm4(sptr(&sH[0][mb + 16 + (l & 7) + ((l >> 3) & 1) * 8][k0 + (l >> 4) * 8]),
                      a1[0], a1[1], a1[2], a1[3]);
                ldsm4(sptr(&sW[0][nb + ((l >> 4) << 3) + (l & 7)][k0 + ((l >> 3) & 1) * 8]),
                      bw[0], bw[1], bw[2], bw[3]);
                mma16816(acc[0][0], a0, bw[0], bw[1]);
                mma16816(acc[0][1], a0, bw[2], bw[3]);
                mma16816(acc[1][0], a1, bw[0], bw[1]);
                mma16816(acc[1][1], a1, bw[2], bw[3]);
            }
        }
        __syncthreads();   // protect smem before next r0 iteration refill

        int qm = l >> 2, qn = (l & 3) * 2;
#pragma unroll
        for (int mi = 0; mi < 2; mi++)
#pragma unroll
            for (int ni = 0; ni < 2; ni++) {
                int lr   = mb + mi * 16 + qm;
                int ocol = oc0 + nb + ni * 8 + qn;
                float* c4 = acc[mi][ni];
                if (!routed || lr < nrem)
                    *(float2*)&yout[(size_t)(rbase + r0 + lr) * HDIM + ocol] =
                        make_float2(c4[0], c4[1]);
                if (!routed || lr + 8 < nrem)
                    *(float2*)&yout[(size_t)(rbase + r0 + lr + 8) * HDIM + ocol] =
                        make_float2(c4[2], c4[3]);
            }
        if (!routed) break;
    }
}

// ---------------------------------------------------------------------------
// Combine: y[t] += sum_k tw[t,k] * yrout[slot(t,k)]
// ---------------------------------------------------------------------------
__global__ __launch_bounds__(256) void combine_kernel(float* __restrict__ y)
{
    int t = blockIdx.x;
    __shared__ int   slot4[TOPK];
    __shared__ float w4[TOPK];
    int tid = threadIdx.x;
    if (tid < TOPK) {
        int a = t * TOPK + tid;
        int e = g_topk_idx[a];
        int p = g_pos[a];
        slot4[tid] = (p < CAP) ? (e * CAP + p) : -1;
        w4[tid]    = g_topk_w[a];
    }
    __syncthreads();
    for (int hh = tid; hh < HDIM; hh += 256) {
        float acc = y[(size_t)t * HDIM + hh];
#pragma unroll
        for (int k = 0; k < TOPK; k++) {
            int s = slot4[k];
            if (s >= 0) acc += w4[k] * g_yrout[(size_t)s * HDIM + hh];
        }
        y[(size_t)t * HDIM + hh] = acc;
    }
}

// ---------------------------------------------------------------------------
extern "C" void kernel_launch(void* const* d_in, const int* in_sizes, int n_in,
                              void* d_out, int out_size)
{
    const float* x              = (const float*)d_in[0];
    const float* gate_w         = (const float*)d_in[1];
    const float* gate_scales    = (const float*)d_in[2];
    const float* up_scales      = (const float*)d_in[3];
    const float* down_scales    = (const float*)d_in[4];
    const float* sh_gate_scales = (const float*)d_in[5];
    const float* sh_up_scales   = (const float*)d_in[6];
    const float* sh_down_scales = (const float*)d_in[7];
    const int*   gate_packed    = (const int*)d_in[8];
    const int*   up_packed      = (const int*)d_in[9];
    const int*   down_packed    = (const int*)d_in[10];
    const int*   sh_gate_packed = (const int*)d_in[11];
    const int*   sh_up_packed   = (const int*)d_in[12];
    const int*   sh_down_packed = (const int*)d_in[13];
    float* y = (float*)d_out;

    xcvt_kernel<<<NTOK * HDIM / 1024, 256>>>(x);
    router_kernel<<<NTOK / 16, 256>>>(x, gate_w);
    zero_counts_kernel<<<1, 64>>>();
    hist_kernel<<<NCHUNK, 256>>>();
    dispatch_kernel<<<NCHUNK, 256>>>();

    // Unified routed + shared-expert GEMMs (routed blocks first in x)
    gemm1_mma<<<dim3(NEXP + NSHB1, IDIM / 64), 256>>>(
        gate_packed, up_packed, gate_scales, up_scales,
        sh_gate_packed, sh_up_packed, sh_gate_scales, sh_up_scales);
    gemm2_mma<<<dim3(NEXP + NSHB1, HDIM / 64), 256>>>(
        down_packed, down_scales, sh_down_packed, sh_down_scales, y);

    combine_kernel<<<NTOK, 256>>>(y);
}